// round 4
// baseline (speedup 1.0000x reference)
#include <cuda_runtime.h>
#include <cuda_fp16.h>
#include <cstdint>

#define THREADS 512
#define SCALE 0.0048957583488887505f   // sqrt(pi/2)/256
#define TAU 2e-2f

// smem layout (bytes). Row pitch 272B = 136 halves (conflict-free ldmatrix).
#define EST4_OFF 0                     // float[128][4]
#define KHI_OFF  2048                  // 128 x 272
#define KLO_OFF  (KHI_OFF + 34816)
#define QHI_OFF  (KLO_OFF + 34816)
#define SHI_OFF  (QHI_OFF + 34816)     // 256 x 272
#define SMEM_TOTAL (SHI_OFF + 69632)   // 176128

__device__ __forceinline__ uint32_t smem_u32(const void* p) {
    uint32_t a;
    asm("{ .reg .u64 t; cvta.to.shared.u64 t, %1; cvt.u32.u64 %0, t; }"
        : "=r"(a) : "l"(p));
    return a;
}

__device__ __forceinline__ void ldsm_x4(uint32_t* r, uint32_t a) {
    asm volatile("ldmatrix.sync.aligned.m8n8.x4.shared.b16 {%0,%1,%2,%3}, [%4];"
                 : "=r"(r[0]), "=r"(r[1]), "=r"(r[2]), "=r"(r[3]) : "r"(a));
}
__device__ __forceinline__ void ldsm_x2(uint32_t& r0, uint32_t& r1, uint32_t a) {
    asm volatile("ldmatrix.sync.aligned.m8n8.x2.shared.b16 {%0,%1}, [%2];"
                 : "=r"(r0), "=r"(r1) : "r"(a));
}
__device__ __forceinline__ void mma16816(float* d, const uint32_t* a,
                                         uint32_t b0, uint32_t b1) {
    asm volatile(
        "mma.sync.aligned.m16n8k16.row.col.f32.f16.f16.f32 "
        "{%0,%1,%2,%3}, {%4,%5,%6,%7}, {%8,%9}, {%0,%1,%2,%3};"
        : "+f"(d[0]), "+f"(d[1]), "+f"(d[2]), "+f"(d[3])
        : "r"(a[0]), "r"(a[1]), "r"(a[2]), "r"(a[3]), "r"(b0), "r"(b1));
}

__global__ void __launch_bounds__(THREADS, 1)
qjl_fused(const float* __restrict__ qry, const float* __restrict__ key,
          const float* __restrict__ Sg, float* __restrict__ out, int ntok) {
    extern __shared__ char smem[];
    const uint32_t sb = smem_u32(smem);
    const int tid = threadIdx.x, wid = tid >> 5, l = tid & 31;
    const int tok_base = blockIdx.x * 128;

    // ---- stage key hi/lo + q hi [128 tok x 128 d] ----
    for (int u = tid; u < 4096; u += THREADS) {
        int row = u >> 5, c4 = u & 31;
        int tok = tok_base + row; if (tok >= ntok) tok = ntok - 1;
        float4 v = __ldg((const float4*)(key + (size_t)tok * 128) + c4);
        __half hx = __float2half_rn(v.x), hy = __float2half_rn(v.y);
        __half hz = __float2half_rn(v.z), hw = __float2half_rn(v.w);
        __half2* dh = (__half2*)(smem + KHI_OFF + row * 272 + c4 * 8);
        dh[0] = __halves2half2(hx, hy); dh[1] = __halves2half2(hz, hw);
        __half2* dl = (__half2*)(smem + KLO_OFF + row * 272 + c4 * 8);
        dl[0] = __halves2half2(__float2half_rn(v.x - __half2float(hx)),
                               __float2half_rn(v.y - __half2float(hy)));
        dl[1] = __halves2half2(__float2half_rn(v.z - __half2float(hz)),
                               __float2half_rn(v.w - __half2float(hw)));
        float4 w = __ldg((const float4*)(qry + (size_t)tok * 128) + c4);
        __half2* dq = (__half2*)(smem + QHI_OFF + row * 272 + c4 * 8);
        dq[0] = __halves2half2(__float2half_rn(w.x), __float2half_rn(w.y));
        dq[1] = __halves2half2(__float2half_rn(w.z), __float2half_rn(w.w));
    }
    // ---- stage S hi [256 p x 128 d] ----
    for (int u = tid; u < 8192; u += THREADS) {
        int row = u >> 5, c4 = u & 31;
        float4 v = __ldg((const float4*)(Sg + (size_t)row * 128) + c4);
        __half2* dh = (__half2*)(smem + SHI_OFF + row * 272 + c4 * 8);
        dh[0] = __halves2half2(__float2half_rn(v.x), __float2half_rn(v.y));
        dh[1] = __halves2half2(__float2half_rn(v.z), __float2half_rn(v.w));
    }
    __syncthreads();

    // lane/warp fragment offsets (bytes)
    const uint32_t a_off = (uint32_t)(wid >> 2) * (32 * 272)
                         + (uint32_t)(l & 15) * 272 + (uint32_t)(l >> 4) * 16;
    const uint32_t b_off = (uint32_t)(wid & 3) * (64 * 272)
                         + (uint32_t)(l & 7) * 272 + (uint32_t)((l >> 3) & 1) * 16;

    float acc[2][8][4];
    #pragma unroll
    for (int mt = 0; mt < 2; mt++)
        #pragma unroll
        for (int nt = 0; nt < 8; nt++)
            #pragma unroll
            for (int j = 0; j < 4; j++) acc[mt][nt][j] = 0.f;

    // ---- fused k-projection: (k_hi + k_lo) * S_hi, B loaded once per (ks,nt) ----
    #pragma unroll
    for (int ks = 0; ks < 8; ks++) {
        uint32_t aaddr = sb + KHI_OFF + a_off + ks * 32;
        uint32_t H0[4], H1[4], L0[4], L1[4];
        ldsm_x4(H0, aaddr);
        ldsm_x4(H1, aaddr + 16 * 272);
        ldsm_x4(L0, aaddr + (KLO_OFF - KHI_OFF));
        ldsm_x4(L1, aaddr + (KLO_OFF - KHI_OFF) + 16 * 272);
        #pragma unroll
        for (int nt = 0; nt < 8; nt++) {
            uint32_t b0, b1;
            ldsm_x2(b0, b1, sb + SHI_OFF + b_off + nt * (8 * 272) + ks * 32);
            mma16816(acc[0][nt], H0, b0, b1);
            mma16816(acc[1][nt], H1, b0, b1);
            mma16816(acc[0][nt], L0, b0, b1);
            mma16816(acc[1][nt], L1, b0, b1);
        }
    }

    // ---- signs (+ exact fp32 fixup for |proj| < TAU) ----
    uint32_t m0 = 0, m1 = 0;
    #pragma unroll
    for (int mt = 0; mt < 2; mt++)
        #pragma unroll
        for (int nt = 0; nt < 8; nt++)
            #pragma unroll
            for (int j = 0; j < 4; j++) {
                float v = acc[mt][nt][j];
                if (fabsf(v) < TAU) {
                    int row = (wid >> 2) * 32 + mt * 16 + (l >> 2) + (j >> 1) * 8;
                    int tok = tok_base + row; if (tok >= ntok) tok = ntok - 1;
                    int proj = (wid & 3) * 64 + nt * 8 + (l & 3) * 2 + (j & 1);
                    const float* kr = key + (size_t)tok * 128;
                    const float* sr = Sg + (size_t)proj * 128;
                    float ex = 0.f;
                    for (int d = 0; d < 128; d++) ex = fmaf(__ldg(kr + d), __ldg(sr + d), ex);
                    v = ex;
                }
                int id = mt * 32 + nt * 4 + j;
                uint32_t bit = (v > 0.f) ? 1u : 0u;
                if (id < 32) m0 |= bit << id; else m1 |= bit << (id - 32);
            }

    // ---- q-projection: single fp16 pass (reuse acc) ----
    #pragma unroll
    for (int mt = 0; mt < 2; mt++)
        #pragma unroll
        for (int nt = 0; nt < 8; nt++)
            #pragma unroll
            for (int j = 0; j < 4; j++) acc[mt][nt][j] = 0.f;
    #pragma unroll
    for (int ks = 0; ks < 8; ks++) {
        uint32_t aaddr = sb + QHI_OFF + a_off + ks * 32;
        uint32_t A0[4], A1[4];
        ldsm_x4(A0, aaddr);
        ldsm_x4(A1, aaddr + 16 * 272);
        #pragma unroll
        for (int nt = 0; nt < 8; nt++) {
            uint32_t b0, b1;
            ldsm_x2(b0, b1, sb + SHI_OFF + b_off + nt * (8 * 272) + ks * 32);
            mma16816(acc[0][nt], A0, b0, b1);
            mma16816(acc[1][nt], A1, b0, b1);
        }
    }

    // ---- epilogue: signed reduction over p, deterministic ----
    float* est4 = (float*)smem;   // [128][4]  (EST4_OFF = 0)
    #pragma unroll
    for (int mt = 0; mt < 2; mt++)
        #pragma unroll
        for (int h = 0; h < 2; h++) {
            float s = 0.f;
            #pragma unroll
            for (int nt = 0; nt < 8; nt++)
                #pragma unroll
                for (int jj = 0; jj < 2; jj++) {
                    int j = h * 2 + jj;
                    int id = mt * 32 + nt * 4 + j;
                    uint32_t bit = ((id < 32) ? (m0 >> id) : (m1 >> (id - 32))) & 1u;
                    float v = acc[mt][nt][j];
                    s += bit ? v : -v;
                }
            s += __shfl_xor_sync(0xFFFFFFFFu, s, 1);
            s += __shfl_xor_sync(0xFFFFFFFFu, s, 2);
            if ((l & 3) == 0) {
                int row = (wid >> 2) * 32 + mt * 16 + h * 8 + (l >> 2);
                est4[row * 4 + (wid & 3)] = s;
            }
        }
    __syncthreads();
    if (tid < 128) {
        int tok = tok_base + tid;
        if (tok < ntok) {
            float e = (est4[tid * 4 + 0] + est4[tid * 4 + 1])
                    + (est4[tid * 4 + 2] + est4[tid * 4 + 3]);
            out[tok] = SCALE * e;
        }
    }
}

extern "C" void kernel_launch(void* const* d_in, const int* in_sizes, int n_in,
                              void* d_out, int out_size) {
    const float* q = (const float*)d_in[0];
    const float* k = (const float*)d_in[1];
    const float* S = (const float*)d_in[2];
    float* out = (float*)d_out;

    int ntok = in_sizes[0] / 128;
    int ntiles = (ntok + 127) / 128;

    cudaFuncSetAttribute(qjl_fused, cudaFuncAttributeMaxDynamicSharedMemorySize,
                         SMEM_TOTAL);
    qjl_fused<<<ntiles, THREADS, SMEM_TOTAL>>>(q, k, S, out, ntok);
}

// round 5
// speedup vs baseline: 2.2823x; 2.2823x over previous
#include <cuda_runtime.h>
#include <cuda_fp16.h>
#include <cstdint>

#define THREADS 1024
#define SCALE 0.0048957583488887505f   // sqrt(pi/2)/256
#define TAU 2e-2f

// smem layout (bytes). Row pitch 272B = 136 halves (conflict-free ldmatrix).
#define EST_OFF 0                      // float[128][8]
#define KQ_OFF  4096                   // 128 x 272  (k_hi, later q_hi)
#define S_OFF   (KQ_OFF + 34816)       // 256 x 272
#define SMEM_TOTAL (S_OFF + 69632)     // 108544

__device__ __forceinline__ uint32_t smem_u32(const void* p) {
    uint32_t a;
    asm("{ .reg .u64 t; cvta.to.shared.u64 t, %1; cvt.u32.u64 %0, t; }"
        : "=r"(a) : "l"(p));
    return a;
}
__device__ __forceinline__ void ldsm_x4(uint32_t* r, uint32_t a) {
    asm volatile("ldmatrix.sync.aligned.m8n8.x4.shared.b16 {%0,%1,%2,%3}, [%4];"
                 : "=r"(r[0]), "=r"(r[1]), "=r"(r[2]), "=r"(r[3]) : "r"(a));
}
__device__ __forceinline__ void ldsm_x2(uint32_t& r0, uint32_t& r1, uint32_t a) {
    asm volatile("ldmatrix.sync.aligned.m8n8.x2.shared.b16 {%0,%1}, [%2];"
                 : "=r"(r0), "=r"(r1) : "r"(a));
}
__device__ __forceinline__ void mma16816(float* d, const uint32_t* a,
                                         uint32_t b0, uint32_t b1) {
    asm volatile(
        "mma.sync.aligned.m16n8k16.row.col.f32.f16.f16.f32 "
        "{%0,%1,%2,%3}, {%4,%5,%6,%7}, {%8,%9}, {%0,%1,%2,%3};"
        : "+f"(d[0]), "+f"(d[1]), "+f"(d[2]), "+f"(d[3])
        : "r"(a[0]), "r"(a[1]), "r"(a[2]), "r"(a[3]), "r"(b0), "r"(b1));
}

__global__ void __launch_bounds__(THREADS, 1)
qjl_fused(const float* __restrict__ qry, const float* __restrict__ key,
          const float* __restrict__ Sg, float* __restrict__ out, int ntok) {
    extern __shared__ char smem[];
    const uint32_t sb = smem_u32(smem);
    const int tid = threadIdx.x, wid = tid >> 5, l = tid & 31;
    const int wm = wid >> 3, wn = wid & 7;      // warp grid 4(M) x 8(N)
    const int tok_base = blockIdx.x * 128;

    // ---- stage k_hi [128 tok x 128 d] : 4096 float4-groups / 1024 thr ----
    for (int u = tid; u < 4096; u += THREADS) {
        int row = u >> 5, c4 = u & 31;
        int tok = tok_base + row; if (tok >= ntok) tok = ntok - 1;
        float4 v = __ldg((const float4*)(key + (size_t)tok * 128) + c4);
        __half2* dh = (__half2*)(smem + KQ_OFF + row * 272 + c4 * 8);
        dh[0] = __halves2half2(__float2half_rn(v.x), __float2half_rn(v.y));
        dh[1] = __halves2half2(__float2half_rn(v.z), __float2half_rn(v.w));
    }
    // ---- stage S_hi [256 p x 128 d] ----
    for (int u = tid; u < 8192; u += THREADS) {
        int row = u >> 5, c4 = u & 31;
        float4 v = __ldg((const float4*)(Sg + (size_t)row * 128) + c4);
        __half2* dh = (__half2*)(smem + S_OFF + row * 272 + c4 * 8);
        dh[0] = __halves2half2(__float2half_rn(v.x), __float2half_rn(v.y));
        dh[1] = __halves2half2(__float2half_rn(v.z), __float2half_rn(v.w));
    }
    __syncthreads();

    const uint32_t a_off = (uint32_t)wm * (32 * 272)
                         + (uint32_t)(l & 15) * 272 + (uint32_t)(l >> 4) * 16;
    const uint32_t b_off = (uint32_t)wn * (32 * 272)
                         + (uint32_t)(l & 7) * 272 + (uint32_t)((l >> 3) & 1) * 16;

    float acc[2][4][4];
    #pragma unroll
    for (int mt = 0; mt < 2; mt++)
        #pragma unroll
        for (int nt = 0; nt < 4; nt++)
            #pragma unroll
            for (int j = 0; j < 4; j++) acc[mt][nt][j] = 0.f;

    // ---- k-projection: single fp16 pass ----
    #pragma unroll
    for (int ks = 0; ks < 8; ks++) {
        uint32_t aaddr = sb + KQ_OFF + a_off + ks * 32;
        uint32_t A0[4], A1[4];
        ldsm_x4(A0, aaddr);
        ldsm_x4(A1, aaddr + 16 * 272);
        #pragma unroll
        for (int nt = 0; nt < 4; nt++) {
            uint32_t b0, b1;
            ldsm_x2(b0, b1, sb + S_OFF + b_off + nt * (8 * 272) + ks * 32);
            mma16816(acc[0][nt], A0, b0, b1);
            mma16816(acc[1][nt], A1, b0, b1);
        }
    }

    // ---- signs + near-zero flags (32 slots per lane) ----
    uint32_t sign = 0, flag = 0;
    #pragma unroll
    for (int mt = 0; mt < 2; mt++)
        #pragma unroll
        for (int nt = 0; nt < 4; nt++)
            #pragma unroll
            for (int j = 0; j < 4; j++) {
                int id = mt * 16 + nt * 4 + j;
                float v = acc[mt][nt][j];
                if (v > 0.f) sign |= 1u << id;
                if (fabsf(v) < TAU) flag |= 1u << id;
            }

    // ---- warp-cooperative exact fp32 fixup of flagged slots ----
    for (;;) {
        uint32_t active = __ballot_sync(0xFFFFFFFFu, flag != 0);
        if (!active) break;
        int leader = __ffs(active) - 1;
        int tok = 0, proj = 0, id = 0;
        if (l == leader) {
            id = __ffs(flag) - 1;
            int mt = id >> 4, j = id & 3;
            int nt = (id >> 2) & 3;
            int row = wm * 32 + mt * 16 + (l >> 2) + (j >> 1) * 8;
            tok = tok_base + row; if (tok >= ntok) tok = ntok - 1;
            proj = wn * 32 + nt * 8 + (l & 3) * 2 + (j & 1);
        }
        tok  = __shfl_sync(0xFFFFFFFFu, tok, leader);
        proj = __shfl_sync(0xFFFFFFFFu, proj, leader);
        const float* kr = key + (size_t)tok * 128 + l * 4;
        const float* sr = Sg + (size_t)proj * 128 + l * 4;
        float p = 0.f;
        #pragma unroll
        for (int d = 0; d < 4; d++) p = fmaf(__ldg(kr + d), __ldg(sr + d), p);
        #pragma unroll
        for (int off = 16; off > 0; off >>= 1)
            p += __shfl_xor_sync(0xFFFFFFFFu, p, off);
        if (l == leader) {
            if (p > 0.f) sign |= 1u << id; else sign &= ~(1u << id);
            flag &= flag - 1;
        }
    }

    __syncthreads();   // everyone done reading k smem

    // ---- stage q_hi into the same buffer ----
    for (int u = tid; u < 4096; u += THREADS) {
        int row = u >> 5, c4 = u & 31;
        int tok = tok_base + row; if (tok >= ntok) tok = ntok - 1;
        float4 v = __ldg((const float4*)(qry + (size_t)tok * 128) + c4);
        __half2* dh = (__half2*)(smem + KQ_OFF + row * 272 + c4 * 8);
        dh[0] = __halves2half2(__float2half_rn(v.x), __float2half_rn(v.y));
        dh[1] = __halves2half2(__float2half_rn(v.z), __float2half_rn(v.w));
    }
    __syncthreads();

    // ---- q-projection: single fp16 pass (reuse acc) ----
    #pragma unroll
    for (int mt = 0; mt < 2; mt++)
        #pragma unroll
        for (int nt = 0; nt < 4; nt++)
            #pragma unroll
            for (int j = 0; j < 4; j++) acc[mt][nt][j] = 0.f;
    #pragma unroll
    for (int ks = 0; ks < 8; ks++) {
        uint32_t aaddr = sb + KQ_OFF + a_off + ks * 32;
        uint32_t A0[4], A1[4];
        ldsm_x4(A0, aaddr);
        ldsm_x4(A1, aaddr + 16 * 272);
        #pragma unroll
        for (int nt = 0; nt < 4; nt++) {
            uint32_t b0, b1;
            ldsm_x2(b0, b1, sb + S_OFF + b_off + nt * (8 * 272) + ks * 32);
            mma16816(acc[0][nt], A0, b0, b1);
            mma16816(acc[1][nt], A1, b0, b1);
        }
    }

    // ---- epilogue: signed reduction over p, deterministic ----
    float* est = (float*)smem;   // [128][8]
    #pragma unroll
    for (int mt = 0; mt < 2; mt++)
        #pragma unroll
        for (int h = 0; h < 2; h++) {
            float s = 0.f;
            #pragma unroll
            for (int nt = 0; nt < 4; nt++)
                #pragma unroll
                for (int jj = 0; jj < 2; jj++) {
                    int j = h * 2 + jj;
                    int id = mt * 16 + nt * 4 + j;
                    float v = acc[mt][nt][j];
                    s += ((sign >> id) & 1u) ? v : -v;
                }
            s += __shfl_xor_sync(0xFFFFFFFFu, s, 1);
            s += __shfl_xor_sync(0xFFFFFFFFu, s, 2);
            if ((l & 3) == 0) {
                int row = wm * 32 + mt * 16 + h * 8 + (l >> 2);
                est[row * 8 + wn] = s;
            }
        }
    __syncthreads();
    if (tid < 128) {
        int tok = tok_base + tid;
        if (tok < ntok) {
            const float* e = est + tid * 8;
            float r = ((e[0] + e[1]) + (e[2] + e[3]))
                    + ((e[4] + e[5]) + (e[6] + e[7]));
            out[tok] = SCALE * r;
        }
    }
}

extern "C" void kernel_launch(void* const* d_in, const int* in_sizes, int n_in,
                              void* d_out, int out_size) {
    const float* q = (const float*)d_in[0];
    const float* k = (const float*)d_in[1];
    const float* S = (const float*)d_in[2];
    float* out = (float*)d_out;

    int ntok = in_sizes[0] / 128;
    int ntiles = (ntok + 127) / 128;

    cudaFuncSetAttribute(qjl_fused, cudaFuncAttributeMaxDynamicSharedMemorySize,
                         SMEM_TOTAL);
    qjl_fused<<<ntiles, THREADS, SMEM_TOTAL>>>(q, k, S, out, ntok);
}

// round 7
// speedup vs baseline: 3.2867x; 1.4401x over previous
#include <cuda_runtime.h>
#include <cuda_fp16.h>
#include <cstdint>

#define THREADS 512
#define SCALE 0.0048957583488887505f   // sqrt(pi/2)/256
#define TAU 2e-2f

// smem layout (bytes). Row pitch 272B = 136 halves (conflict-free ldmatrix).
#define EST_OFF 0                      // float[64][8]
#define K_OFF   2048                   // 64 x 272
#define Q_OFF   (K_OFF + 17408)        // 64 x 272
#define S_OFF   (Q_OFF + 17408)        // 256 x 272
#define SMEM_TOTAL (S_OFF + 69632)     // 106496

// S pre-converted to fp16 in the exact 272-pitch smem image layout
__device__ __align__(16) unsigned char g_Sfp16[69632];

__device__ __forceinline__ uint32_t smem_u32(const void* p) {
    uint32_t a;
    asm("{ .reg .u64 t; cvta.to.shared.u64 t, %1; cvt.u32.u64 %0, t; }"
        : "=r"(a) : "l"(p));
    return a;
}
__device__ __forceinline__ void ldsm_x4(uint32_t* r, uint32_t a) {
    asm volatile("ldmatrix.sync.aligned.m8n8.x4.shared.b16 {%0,%1,%2,%3}, [%4];"
                 : "=r"(r[0]), "=r"(r[1]), "=r"(r[2]), "=r"(r[3]) : "r"(a));
}
__device__ __forceinline__ void ldsm_x2(uint32_t& r0, uint32_t& r1, uint32_t a) {
    asm volatile("ldmatrix.sync.aligned.m8n8.x2.shared.b16 {%0,%1}, [%2];"
                 : "=r"(r0), "=r"(r1) : "r"(a));
}
__device__ __forceinline__ void mma16816(float* d, const uint32_t* a,
                                         uint32_t b0, uint32_t b1) {
    asm volatile(
        "mma.sync.aligned.m16n8k16.row.col.f32.f16.f16.f32 "
        "{%0,%1,%2,%3}, {%4,%5,%6,%7}, {%8,%9}, {%0,%1,%2,%3};"
        : "+f"(d[0]), "+f"(d[1]), "+f"(d[2]), "+f"(d[3])
        : "r"(a[0]), "r"(a[1]), "r"(a[2]), "r"(a[3]), "r"(b0), "r"(b1));
}
__device__ __forceinline__ void cp16(uint32_t saddr, const void* gaddr) {
    asm volatile("cp.async.cg.shared.global [%0], [%1], 16;"
                 :: "r"(saddr), "l"(gaddr) : "memory");
}

// ---------------------------------------------------------------------------
// Kernel 0: convert S (256x128 fp32) -> fp16 image with 272B row pitch.
// 4096 threads, each handles 8 consecutive floats -> one 16B store.
// ---------------------------------------------------------------------------
__global__ void qjl_conv_S(const float* __restrict__ S) {
    int i = blockIdx.x * blockDim.x + threadIdx.x;  // 0..4095
    int row = i >> 4, g = i & 15;                   // 16 groups of 8 per row
    const float4* src = (const float4*)(S + (size_t)row * 128 + g * 8);
    float4 a = __ldg(src), b = __ldg(src + 1);
    __align__(16) __half2 o[4];
    o[0] = __halves2half2(__float2half_rn(a.x), __float2half_rn(a.y));
    o[1] = __halves2half2(__float2half_rn(a.z), __float2half_rn(a.w));
    o[2] = __halves2half2(__float2half_rn(b.x), __float2half_rn(b.y));
    o[3] = __halves2half2(__float2half_rn(b.z), __float2half_rn(b.w));
    *(uint4*)(g_Sfp16 + row * 272 + g * 16) = *(const uint4*)o;
}

// ---------------------------------------------------------------------------
// Main kernel: 64 tokens x 256 projections per CTA, 2 CTAs/SM.
// ---------------------------------------------------------------------------
__global__ void __launch_bounds__(THREADS, 2)
qjl_fused(const float* __restrict__ qry, const float* __restrict__ key,
          const float* __restrict__ Sg, float* __restrict__ out, int ntok) {
    extern __shared__ char smem[];
    const uint32_t sb = smem_u32(smem);
    const int tid = threadIdx.x, wid = tid >> 5, l = tid & 31;
    const int wm = wid >> 3, wn = wid & 7;      // warp grid 2(M) x 8(N)
    const int tok_base = blockIdx.x * 64;

    // ---- S image -> smem via cp.async (4352 x 16B) ----
    for (int u = tid; u < 4352; u += THREADS)
        cp16(sb + S_OFF + u * 16, g_Sfp16 + u * 16);
    asm volatile("cp.async.commit_group;" ::: "memory");

    // ---- stage k_hi and q_hi [64 tok x 128 d] ----
    for (int u = tid; u < 2048; u += THREADS) {
        int row = u >> 5, c4 = u & 31;
        int tok = tok_base + row; if (tok >= ntok) tok = ntok - 1;
        float4 v = __ldg((const float4*)(key + (size_t)tok * 128) + c4);
        __half2* dk = (__half2*)(smem + K_OFF + row * 272 + c4 * 8);
        dk[0] = __halves2half2(__float2half_rn(v.x), __float2half_rn(v.y));
        dk[1] = __halves2half2(__float2half_rn(v.z), __float2half_rn(v.w));
        float4 w = __ldg((const float4*)(qry + (size_t)tok * 128) + c4);
        __half2* dq = (__half2*)(smem + Q_OFF + row * 272 + c4 * 8);
        dq[0] = __halves2half2(__float2half_rn(w.x), __float2half_rn(w.y));
        dq[1] = __halves2half2(__float2half_rn(w.z), __float2half_rn(w.w));
    }
    asm volatile("cp.async.wait_group 0;" ::: "memory");
    __syncthreads();

    const uint32_t a_off = (uint32_t)wm * (32 * 272)
                         + (uint32_t)(l & 15) * 272 + (uint32_t)(l >> 4) * 16;
    const uint32_t b_off = (uint32_t)wn * (32 * 272)
                         + (uint32_t)(l & 7) * 272 + (uint32_t)((l >> 3) & 1) * 16;

    float acc[2][4][4];
    #pragma unroll
    for (int mt = 0; mt < 2; mt++)
        #pragma unroll
        for (int nt = 0; nt < 4; nt++)
            #pragma unroll
            for (int j = 0; j < 4; j++) acc[mt][nt][j] = 0.f;

    // ---- k-projection: single fp16 pass ----
    #pragma unroll
    for (int ks = 0; ks < 8; ks++) {
        uint32_t aaddr = sb + K_OFF + a_off + ks * 32;
        uint32_t A0[4], A1[4];
        ldsm_x4(A0, aaddr);
        ldsm_x4(A1, aaddr + 16 * 272);
        #pragma unroll
        for (int nt = 0; nt < 4; nt++) {
            uint32_t b0, b1;
            ldsm_x2(b0, b1, sb + S_OFF + b_off + nt * (8 * 272) + ks * 32);
            mma16816(acc[0][nt], A0, b0, b1);
            mma16816(acc[1][nt], A1, b0, b1);
        }
    }

    // ---- signs + near-zero flags ----
    uint32_t sign = 0, flag = 0;
    #pragma unroll
    for (int mt = 0; mt < 2; mt++)
        #pragma unroll
        for (int nt = 0; nt < 4; nt++)
            #pragma unroll
            for (int j = 0; j < 4; j++) {
                int id = mt * 16 + nt * 4 + j;
                float v = acc[mt][nt][j];
                if (v > 0.f) sign |= 1u << id;
                if (fabsf(v) < TAU) flag |= 1u << id;
            }

    // ---- warp-cooperative exact fp32 fixup ----
    for (;;) {
        uint32_t active = __ballot_sync(0xFFFFFFFFu, flag != 0);
        if (!active) break;
        int leader = __ffs(active) - 1;
        int tok = 0, proj = 0, id = 0;
        if (l == leader) {
            id = __ffs(flag) - 1;
            int mt = id >> 4, j = id & 3;
            int nt = (id >> 2) & 3;
            int row = wm * 32 + mt * 16 + (l >> 2) + (j >> 1) * 8;
            tok = tok_base + row; if (tok >= ntok) tok = ntok - 1;
            proj = wn * 32 + nt * 8 + (l & 3) * 2 + (j & 1);
        }
        tok  = __shfl_sync(0xFFFFFFFFu, tok, leader);
        proj = __shfl_sync(0xFFFFFFFFu, proj, leader);
        const float* kr = key + (size_t)tok * 128 + l * 4;
        const float* sr = Sg + (size_t)proj * 128 + l * 4;
        float p = 0.f;
        #pragma unroll
        for (int d = 0; d < 4; d++) p = fmaf(__ldg(kr + d), __ldg(sr + d), p);
        #pragma unroll
        for (int off = 16; off > 0; off >>= 1)
            p += __shfl_xor_sync(0xFFFFFFFFu, p, off);
        if (l == leader) {
            if (p > 0.f) sign |= 1u << id; else sign &= ~(1u << id);
            flag &= flag - 1;
        }
    }

    // ---- q-projection (q already staged; no sync needed) ----
    #pragma unroll
    for (int mt = 0; mt < 2; mt++)
        #pragma unroll
        for (int nt = 0; nt < 4; nt++)
            #pragma unroll
            for (int j = 0; j < 4; j++) acc[mt][nt][j] = 0.f;
    #pragma unroll
    for (int ks = 0; ks < 8; ks++) {
        uint32_t aaddr = sb + Q_OFF + a_off + ks * 32;
        uint32_t A0[4], A1[4];
        ldsm_x4(A0, aaddr);
        ldsm_x4(A1, aaddr + 16 * 272);
        #pragma unroll
        for (int nt = 0; nt < 4; nt++) {
            uint32_t b0, b1;
            ldsm_x2(b0, b1, sb + S_OFF + b_off + nt * (8 * 272) + ks * 32);
            mma16816(acc[0][nt], A0, b0, b1);
            mma16816(acc[1][nt], A1, b0, b1);
        }
    }

    // ---- epilogue: signed reduction over p, deterministic ----
    float* est = (float*)smem;   // [64][8]
    #pragma unroll
    for (int mt = 0; mt < 2; mt++)
        #pragma unroll
        for (int h = 0; h < 2; h++) {
            float s = 0.f;
            #pragma unroll
            for (int nt = 0; nt < 4; nt++)
                #pragma unroll
                for (int jj = 0; jj < 2; jj++) {
                    int j = h * 2 + jj;
                    int id = mt * 16 + nt * 4 + j;
                    float v = acc[mt][nt][j];
                    s += ((sign >> id) & 1u) ? v : -v;
                }
            s += __shfl_xor_sync(0xFFFFFFFFu, s, 1);
            s += __shfl_xor_sync(0xFFFFFFFFu, s, 2);
            if ((l & 3) == 0) {
                int row = wm * 32 + mt * 16 + h * 8 + (l >> 2);
                est[row * 8 + wn] = s;
            }
        }
    __syncthreads();
    if (tid < 64) {
        int tok = tok_base + tid;
        if (tok < ntok) {
            const float* e = est + tid * 8;
            float r = ((e[0] + e[1]) + (e[2] + e[3]))
                    + ((e[4] + e[5]) + (e[6] + e[7]));
            out[tok] = SCALE * r;
        }
    }
}

extern "C" void kernel_launch(void* const* d_in, const int* in_sizes, int n_in,
                              void* d_out, int out_size) {
    const float* q = (const float*)d_in[0];
    const float* k = (const float*)d_in[1];
    const float* S = (const float*)d_in[2];
    float* out = (float*)d_out;

    int ntok = in_sizes[0] / 128;
    int ntiles = (ntok + 63) / 64;

    qjl_conv_S<<<16, 256>>>(S);

    cudaFuncSetAttribute(qjl_fused, cudaFuncAttributeMaxDynamicSharedMemorySize,
                         SMEM_TOTAL);
    qjl_fused<<<ntiles, THREADS, SMEM_TOTAL>>>(q, k, S, out, ntok);
}

// round 8
// speedup vs baseline: 3.3462x; 1.0181x over previous
#include <cuda_runtime.h>
#include <cuda_fp16.h>
#include <cstdint>

#define THREADS 512
#define SCALE 0.0048957583488887505f   // sqrt(pi/2)/256
#define TAU 2e-2f

// smem layout (bytes). Row pitch 272B = 136 halves (conflict-free ldmatrix).
#define EST_OFF 0                      // float[64][8]
#define K_OFF   2048                   // 64 x 272
#define Q_OFF   (K_OFF + 17408)        // 64 x 272
#define S_OFF   (Q_OFF + 17408)        // 256 x 272
#define SMEM_TOTAL (S_OFF + 69632)     // 106496

// S pre-converted to fp16 in the exact 272-pitch smem image layout
__device__ __align__(16) unsigned char g_Sfp16[69632];

__device__ __forceinline__ uint32_t smem_u32(const void* p) {
    uint32_t a;
    asm("{ .reg .u64 t; cvta.to.shared.u64 t, %1; cvt.u32.u64 %0, t; }"
        : "=r"(a) : "l"(p));
    return a;
}
__device__ __forceinline__ void ldsm_x4(uint32_t* r, uint32_t a) {
    asm volatile("ldmatrix.sync.aligned.m8n8.x4.shared.b16 {%0,%1,%2,%3}, [%4];"
                 : "=r"(r[0]), "=r"(r[1]), "=r"(r[2]), "=r"(r[3]) : "r"(a));
}
__device__ __forceinline__ void mma16816(float* d, const uint32_t* a,
                                         uint32_t b0, uint32_t b1) {
    asm volatile(
        "mma.sync.aligned.m16n8k16.row.col.f32.f16.f16.f32 "
        "{%0,%1,%2,%3}, {%4,%5,%6,%7}, {%8,%9}, {%0,%1,%2,%3};"
        : "+f"(d[0]), "+f"(d[1]), "+f"(d[2]), "+f"(d[3])
        : "r"(a[0]), "r"(a[1]), "r"(a[2]), "r"(a[3]), "r"(b0), "r"(b1));
}
__device__ __forceinline__ void cp16(uint32_t saddr, const void* gaddr) {
    asm volatile("cp.async.cg.shared.global [%0], [%1], 16;"
                 :: "r"(saddr), "l"(gaddr) : "memory");
}

// ---------------------------------------------------------------------------
// Kernel 0: convert S (256x128 fp32) -> fp16 image with 272B row pitch.
// ---------------------------------------------------------------------------
__global__ void qjl_conv_S(const float* __restrict__ S) {
    int i = blockIdx.x * blockDim.x + threadIdx.x;  // 0..4095
    int row = i >> 4, g = i & 15;                   // 16 groups of 8 per row
    const float4* src = (const float4*)(S + (size_t)row * 128 + g * 8);
    float4 a = __ldg(src), b = __ldg(src + 1);
    __align__(16) __half2 o[4];
    o[0] = __halves2half2(__float2half_rn(a.x), __float2half_rn(a.y));
    o[1] = __halves2half2(__float2half_rn(a.z), __float2half_rn(a.w));
    o[2] = __halves2half2(__float2half_rn(b.x), __float2half_rn(b.y));
    o[3] = __halves2half2(__float2half_rn(b.z), __float2half_rn(b.w));
    *(uint4*)(g_Sfp16 + row * 272 + g * 16) = *(const uint4*)o;
}

// ---------------------------------------------------------------------------
// Main kernel: persistent, 2 CTAs/SM; each CTA grid-strides over 64-token
// tiles. S staged ONCE per CTA via cp.async.
// ---------------------------------------------------------------------------
__global__ void __launch_bounds__(THREADS, 2)
qjl_fused(const float* __restrict__ qry, const float* __restrict__ key,
          const float* __restrict__ Sg, float* __restrict__ out,
          int ntok, int ntiles) {
    extern __shared__ char smem[];
    const uint32_t sb = smem_u32(smem);
    const int tid = threadIdx.x, wid = tid >> 5, l = tid & 31;
    const int wm = wid >> 3, wn = wid & 7;      // warp grid 2(M) x 8(N)

    // ---- S image -> smem once (4352 x 16B cp.async) ----
    for (int u = tid; u < 4352; u += THREADS)
        cp16(sb + S_OFF + u * 16, g_Sfp16 + u * 16);
    asm volatile("cp.async.commit_group;" ::: "memory");
    asm volatile("cp.async.wait_group 0;" ::: "memory");

    const uint32_t a_base = (uint32_t)wm * (32 * 272)
                          + (uint32_t)(l & 15) * 272 + (uint32_t)(l >> 4) * 16;
    // B x4 base: lanes 0-15 -> n-tile nt2*2, lanes 16-31 -> nt2*2+1
    const uint32_t b_base = sb + S_OFF + (uint32_t)wn * (32 * 272)
                          + (uint32_t)(l >> 4) * (8 * 272)
                          + (uint32_t)(l & 7) * 272 + (uint32_t)((l >> 3) & 1) * 16;

    for (int tile = blockIdx.x; tile < ntiles; tile += gridDim.x) {
        const int tok_base = tile * 64;

        // ---- stage k_hi and q_hi [64 tok x 128 d] ----
        for (int u = tid; u < 2048; u += THREADS) {
            int row = u >> 5, c4 = u & 31;
            int tok = tok_base + row; if (tok >= ntok) tok = ntok - 1;
            float4 v = __ldg((const float4*)(key + (size_t)tok * 128) + c4);
            __half2* dk = (__half2*)(smem + K_OFF + row * 272 + c4 * 8);
            dk[0] = __halves2half2(__float2half_rn(v.x), __float2half_rn(v.y));
            dk[1] = __halves2half2(__float2half_rn(v.z), __float2half_rn(v.w));
            float4 w = __ldg((const float4*)(qry + (size_t)tok * 128) + c4);
            __half2* dq = (__half2*)(smem + Q_OFF + row * 272 + c4 * 8);
            dq[0] = __halves2half2(__float2half_rn(w.x), __float2half_rn(w.y));
            dq[1] = __halves2half2(__float2half_rn(w.z), __float2half_rn(w.w));
        }
        __syncthreads();

        float acc[2][4][4];
        #pragma unroll
        for (int mt = 0; mt < 2; mt++)
            #pragma unroll
            for (int nt = 0; nt < 4; nt++)
                #pragma unroll
                for (int j = 0; j < 4; j++) acc[mt][nt][j] = 0.f;

        // ---- k-projection: single fp16 pass ----
        #pragma unroll
        for (int ks = 0; ks < 8; ks++) {
            uint32_t aaddr = sb + K_OFF + a_base + ks * 32;
            uint32_t A0[4], A1[4];
            ldsm_x4(A0, aaddr);
            ldsm_x4(A1, aaddr + 16 * 272);
            #pragma unroll
            for (int nt2 = 0; nt2 < 2; nt2++) {
                uint32_t B[4];
                ldsm_x4(B, b_base + nt2 * (16 * 272) + ks * 32);
                mma16816(acc[0][2 * nt2],     A0, B[0], B[1]);
                mma16816(acc[1][2 * nt2],     A1, B[0], B[1]);
                mma16816(acc[0][2 * nt2 + 1], A0, B[2], B[3]);
                mma16816(acc[1][2 * nt2 + 1], A1, B[2], B[3]);
            }
        }

        // ---- signs + near-zero flags ----
        uint32_t sign = 0, flag = 0;
        #pragma unroll
        for (int mt = 0; mt < 2; mt++)
            #pragma unroll
            for (int nt = 0; nt < 4; nt++)
                #pragma unroll
                for (int j = 0; j < 4; j++) {
                    int id = mt * 16 + nt * 4 + j;
                    float v = acc[mt][nt][j];
                    if (v > 0.f) sign |= 1u << id;
                    if (fabsf(v) < TAU) flag |= 1u << id;
                }

        // ---- warp-cooperative exact fp32 fixup ----
        for (;;) {
            uint32_t active = __ballot_sync(0xFFFFFFFFu, flag != 0);
            if (!active) break;
            int leader = __ffs(active) - 1;
            int tok = 0, proj = 0, id = 0;
            if (l == leader) {
                id = __ffs(flag) - 1;
                int mt = id >> 4, j = id & 3;
                int nt = (id >> 2) & 3;
                int row = wm * 32 + mt * 16 + (l >> 2) + (j >> 1) * 8;
                tok = tok_base + row; if (tok >= ntok) tok = ntok - 1;
                proj = wn * 32 + nt * 8 + (l & 3) * 2 + (j & 1);
            }
            tok  = __shfl_sync(0xFFFFFFFFu, tok, leader);
            proj = __shfl_sync(0xFFFFFFFFu, proj, leader);
            const float* kr = key + (size_t)tok * 128 + l * 4;
            const float* sr = Sg + (size_t)proj * 128 + l * 4;
            float p = 0.f;
            #pragma unroll
            for (int d = 0; d < 4; d++) p = fmaf(__ldg(kr + d), __ldg(sr + d), p);
            #pragma unroll
            for (int off = 16; off > 0; off >>= 1)
                p += __shfl_xor_sync(0xFFFFFFFFu, p, off);
            if (l == leader) {
                if (p > 0.f) sign |= 1u << id; else sign &= ~(1u << id);
                flag &= flag - 1;
            }
        }

        // ---- q-projection (q already staged) ----
        #pragma unroll
        for (int mt = 0; mt < 2; mt++)
            #pragma unroll
            for (int nt = 0; nt < 4; nt++)
                #pragma unroll
                for (int j = 0; j < 4; j++) acc[mt][nt][j] = 0.f;
        #pragma unroll
        for (int ks = 0; ks < 8; ks++) {
            uint32_t aaddr = sb + Q_OFF + a_base + ks * 32;
            uint32_t A0[4], A1[4];
            ldsm_x4(A0, aaddr);
            ldsm_x4(A1, aaddr + 16 * 272);
            #pragma unroll
            for (int nt2 = 0; nt2 < 2; nt2++) {
                uint32_t B[4];
                ldsm_x4(B, b_base + nt2 * (16 * 272) + ks * 32);
                mma16816(acc[0][2 * nt2],     A0, B[0], B[1]);
                mma16816(acc[1][2 * nt2],     A1, B[0], B[1]);
                mma16816(acc[0][2 * nt2 + 1], A0, B[2], B[3]);
                mma16816(acc[1][2 * nt2 + 1], A1, B[2], B[3]);
            }
        }

        // ---- epilogue: signed reduction over p, deterministic ----
        float* est = (float*)smem;   // [64][8]
        #pragma unroll
        for (int mt = 0; mt < 2; mt++)
            #pragma unroll
            for (int h = 0; h < 2; h++) {
                float s = 0.f;
                #pragma unroll
                for (int nt = 0; nt < 4; nt++)
                    #pragma unroll
                    for (int jj = 0; jj < 2; jj++) {
                        int j = h * 2 + jj;
                        int id = mt * 16 + nt * 4 + j;
                        float v = acc[mt][nt][j];
                        s += ((sign >> id) & 1u) ? v : -v;
                    }
                s += __shfl_xor_sync(0xFFFFFFFFu, s, 1);
                s += __shfl_xor_sync(0xFFFFFFFFu, s, 2);
                if ((l & 3) == 0) {
                    int row = wm * 32 + mt * 16 + h * 8 + (l >> 2);
                    est[row * 8 + wn] = s;
                }
            }
        __syncthreads();
        if (tid < 64) {
            int tok = tok_base + tid;
            if (tok < ntok) {
                const float* e = est + tid * 8;
                float r = ((e[0] + e[1]) + (e[2] + e[3]))
                        + ((e[4] + e[5]) + (e[6] + e[7]));
                out[tok] = SCALE * r;
            }
        }
        // next iteration's staging writes K/Q (disjoint from EST); the
        // staging __syncthreads orders EST reads before EST is rewritten.
    }
}

extern "C" void kernel_launch(void* const* d_in, const int* in_sizes, int n_in,
                              void* d_out, int out_size) {
    const float* q = (const float*)d_in[0];
    const float* k = (const float*)d_in[1];
    const float* S = (const float*)d_in[2];
    float* out = (float*)d_out;

    int ntok = in_sizes[0] / 128;
    int ntiles = (ntok + 63) / 64;
    int grid = ntiles < 296 ? ntiles : 296;   // 2 persistent CTAs per SM

    qjl_conv_S<<<16, 256>>>(S);

    cudaFuncSetAttribute(qjl_fused, cudaFuncAttributeMaxDynamicSharedMemorySize,
                         SMEM_TOTAL);
    qjl_fused<<<grid, THREADS, SMEM_TOTAL>>>(q, k, S, out, ntok, ntiles);
}